// round 8
// baseline (speedup 1.0000x reference)
#include <cuda_runtime.h>

#define B_ 4
#define T_ 2048
#define C_ 1024
#define H_ 16
#define D_ 64
#define M_ (B_*T_)

// Scratch (device globals; allocation-free per harness rules)
__device__ float g_x [M_*C_];         // x, tf32-rounded, k-interleaved per 8
__device__ float g_wq[3*C_*C_];       // w_qkv^T: [n][k], tf32, k-interleaved
__device__ float g_wp[C_*C_];         // w_proj^T: [n][k], tf32, k-interleaved
__device__ float g_q [B_*H_*T_*D_];   // [B,H,T,d], tf32, plain
__device__ float g_k [B_*H_*T_*D_];   // [B,H,T,d], tf32, d-interleaved per 8
__device__ float g_v [B_*H_*T_*D_];   // [B,H,T,d], tf32, plain
__device__ float g_ao[M_*C_];         // attn out, [B*T,C], tf32, k-interleaved

// ---------------------------------------------------------------------------
// helpers
// ---------------------------------------------------------------------------
__device__ __forceinline__ unsigned f2tf(float x) {
    unsigned r;
    asm("cvt.rna.tf32.f32 %0, %1;" : "=r"(r) : "f"(x));
    return r;
}
__device__ __forceinline__ float f2tf_f(float x) {
    return __uint_as_float(f2tf(x));
}
__device__ __forceinline__ void mma_tf32(float* d, const unsigned* a,
                                         const unsigned* b, const float* c) {
    asm volatile(
        "mma.sync.aligned.m16n8k8.row.col.f32.tf32.tf32.f32 "
        "{%0,%1,%2,%3}, {%4,%5,%6,%7}, {%8,%9}, {%10,%11,%12,%13};\n"
        : "=f"(d[0]), "=f"(d[1]), "=f"(d[2]), "=f"(d[3])
        : "r"(a[0]), "r"(a[1]), "r"(a[2]), "r"(a[3]),
          "r"(b[0]), "r"(b[1]),
          "f"(c[0]), "f"(c[1]), "f"(c[2]), "f"(c[3]));
}
__device__ __forceinline__ void cp_async16(float* smem, const float* gmem) {
    unsigned saddr = (unsigned)__cvta_generic_to_shared(smem);
    asm volatile("cp.async.cg.shared.global [%0], [%1], 16;\n"
                 :: "r"(saddr), "l"(gmem) : "memory");
}
#define CP_COMMIT() asm volatile("cp.async.commit_group;\n" ::: "memory")
#define CP_WAIT(n)  asm volatile("cp.async.wait_group %0;\n" :: "n"(n) : "memory")

// ---------------------------------------------------------------------------
// Prepack kernels (one-time, memory-bound).
// Interleave map within each 8-group of k:  j -> (j<4) ? 2j : 2(j-4)+1
// so fragment pairs (k, k+4) become adjacent -> LDS.64 in hot loops.
// ---------------------------------------------------------------------------
__global__ __launch_bounds__(256) void pack_rows(const float* __restrict__ in,
                                                 float* __restrict__ out)
{
    size_t gid = (size_t)blockIdx.x * 256 + threadIdx.x;   // one 8-group each
    const float4 a = *(const float4*)(in + gid*8);
    const float4 b = *(const float4*)(in + gid*8 + 4);
    float4 o0 = make_float4(f2tf_f(a.x), f2tf_f(b.x), f2tf_f(a.y), f2tf_f(b.y));
    float4 o1 = make_float4(f2tf_f(a.z), f2tf_f(b.z), f2tf_f(a.w), f2tf_f(b.w));
    *(float4*)(out + gid*8)     = o0;
    *(float4*)(out + gid*8 + 4) = o1;
}

// W [K=1024][N] row-major  ->  out [N][1024] transposed + rounded + interleaved
__global__ __launch_bounds__(256) void pack_wt(const float* __restrict__ W,
                                               float* __restrict__ out, int N)
{
    __shared__ float t[32][33];
    const int n0 = blockIdx.x << 5, k0 = blockIdx.y << 5;
    const int tx = threadIdx.x, ty = threadIdx.y;          // 32 x 8
#pragma unroll
    for (int i = ty; i < 32; i += 8)
        t[i][tx] = W[(size_t)(k0 + i) * N + n0 + tx];
    __syncthreads();
    const int j = tx & 7, grp = tx >> 3;
    const int kp = (grp << 3) + ((j < 4) ? (j << 1) : (((j - 4) << 1) + 1));
#pragma unroll
    for (int i = ty; i < 32; i += 8)
        out[(size_t)(n0 + i) * C_ + k0 + kp] = f2tf_f(t[tx][i]);
}

// ---------------------------------------------------------------------------
// GEMM: 128x128 block, 8 warps (4x2 of 32x64 warp tiles), 256 threads.
// A [m][k], B [n][k], both packed. Smem: LD=32, XOR swizzle
// word' = word ^ ((row&3)<<3)  ->  pad-free, conflict-free LDS.64.
// 3-stage cp.async ring + EXPLICIT kk-level fragment double-buffering:
// kk+1's 12 LDS.64 issue before kk's 16 MMAs, draining under them.
// ---------------------------------------------------------------------------
#define G_TILEW (128*32)
#define G_STAGEW (2*G_TILEW)

__device__ __forceinline__ void gemm_stage(float* smg, const float* Ap,
    const float* Bp, int m0, int n0, int ks, int st, int tid)
{
    float* As = smg + st * G_STAGEW;
    float* Bs = As + G_TILEW;
    const int k0 = ks << 5;
    const int r = tid >> 3, c = (tid & 7) << 2;
    const int cw = c ^ ((r & 3) << 3);           // swizzled chunk position
#pragma unroll
    for (int i = 0; i < 4; i++) {                // 128x32 tile = 1024 f4
        cp_async16(&As[(i*32 + r)*32 + cw], Ap + (size_t)(m0 + i*32 + r)*C_ + k0 + c);
        cp_async16(&Bs[(i*32 + r)*32 + cw], Bp + (size_t)(n0 + i*32 + r)*C_ + k0 + c);
    }
    CP_COMMIT();
}

template<bool SCATTER>
__global__ __launch_bounds__(256, 2) void mma_gemm(
    const float* __restrict__ Ap, const float* __restrict__ Bp,
    const float* __restrict__ bias, float* __restrict__ out)
{
    extern __shared__ float smg[];

    const int tid  = threadIdx.x;
    const int lane = tid & 31, w = tid >> 5;
    const int g = lane >> 2, ctg = lane & 3;
    const int msk = (g & 3) << 3;                // read-side swizzle mask
    const int wm = (w >> 1) << 5;     // 0,32,64,96
    const int wn = (w & 1)  << 6;     // 0,64
    const int m0 = blockIdx.y << 7, n0 = blockIdx.x << 7;

    float acc[2][8][4];
#pragma unroll
    for (int mt = 0; mt < 2; mt++)
#pragma unroll
        for (int nf = 0; nf < 8; nf++)
#pragma unroll
            for (int r = 0; r < 4; r++) acc[mt][nf][r] = 0.f;

    gemm_stage(smg, Ap, Bp, m0, n0, 0, 0, tid);
    gemm_stage(smg, Ap, Bp, m0, n0, 1, 1, tid);

    // fragment double buffers
    unsigned fa[2][2][4];   // [buf][mt][4]
    unsigned fb[2][8][2];   // [buf][nf][2]

    int st = 0, st2 = 2;                         // stage of ks, of ks+2
#pragma unroll 1
    for (int ks = 0; ks < 32; ks++) {
        CP_WAIT(1);
        __syncthreads();
        if (ks + 2 < 32) gemm_stage(smg, Ap, Bp, m0, n0, ks + 2, st2, tid);

        const float* As = smg + st * G_STAGEW;
        const float* Bs = As + G_TILEW;

        // load kk=0 fragments into buf 0
        {
            const int ca = (0 ^ msk) + (ctg << 1);
#pragma unroll
            for (int mt = 0; mt < 2; mt++) {
                int rb = wm + (mt << 4) + g;
                float2 v0 = *(const float2*)&As[(rb  ) * 32 + ca];
                float2 v1 = *(const float2*)&As[(rb+8) * 32 + ca];
                fa[0][mt][0] = __float_as_uint(v0.x);
                fa[0][mt][2] = __float_as_uint(v0.y);
                fa[0][mt][1] = __float_as_uint(v1.x);
                fa[0][mt][3] = __float_as_uint(v1.y);
            }
#pragma unroll
            for (int nf = 0; nf < 8; nf++) {
                float2 bv = *(const float2*)&Bs[(wn + (nf<<3) + g) * 32 + ca];
                fb[0][nf][0] = __float_as_uint(bv.x);
                fb[0][nf][1] = __float_as_uint(bv.y);
            }
        }
#pragma unroll
        for (int kk = 0; kk < 4; kk++) {
            const int cur = kk & 1, nxt = cur ^ 1;
            if (kk < 3) {        // prefetch kk+1 fragments (drain under MMAs)
                const int ca = (((kk+1) << 3) ^ msk) + (ctg << 1);
#pragma unroll
                for (int mt = 0; mt < 2; mt++) {
                    int rb = wm + (mt << 4) + g;
                    float2 v0 = *(const float2*)&As[(rb  ) * 32 + ca];
                    float2 v1 = *(const float2*)&As[(rb+8) * 32 + ca];
                    fa[nxt][mt][0] = __float_as_uint(v0.x);
                    fa[nxt][mt][2] = __float_as_uint(v0.y);
                    fa[nxt][mt][1] = __float_as_uint(v1.x);
                    fa[nxt][mt][3] = __float_as_uint(v1.y);
                }
#pragma unroll
                for (int nf = 0; nf < 8; nf++) {
                    float2 bv = *(const float2*)&Bs[(wn + (nf<<3) + g) * 32 + ca];
                    fb[nxt][nf][0] = __float_as_uint(bv.x);
                    fb[nxt][nf][1] = __float_as_uint(bv.y);
                }
            }
#pragma unroll
            for (int nf = 0; nf < 8; nf++) {
                mma_tf32(acc[0][nf], fa[cur][0], fb[cur][nf], acc[0][nf]);
                mma_tf32(acc[1][nf], fa[cur][1], fb[cur][nf], acc[1][nf]);
            }
        }
        st  = (st  == 2) ? 0 : st  + 1;
        st2 = (st2 == 2) ? 0 : st2 + 1;
    }

    // Epilogue
    const int p0 = ((ctg & 1) << 2) + (ctg >> 1), p1 = p0 + 2;  // interleave pos
#pragma unroll
    for (int mt = 0; mt < 2; mt++) {
#pragma unroll
        for (int nf = 0; nf < 8; nf++) {
            int col = n0 + wn + (nf << 3) + (ctg << 1);
            int r0  = m0 + wm + (mt << 4) + g;
            float b0 = bias[col], b1 = bias[col + 1];
            if (SCATTER) {   // qkv -> g_q/g_k/g_v, tf32-rounded
                int sect = col >> 10, cc = col & 1023;
                int h = cc >> 6, dd = cc & 63;
                float* dst = (sect == 0) ? g_q : (sect == 1) ? g_k : g_v;
                int bb0 = r0 >> 11, t0 = r0 & (T_-1);
                int r1 = r0 + 8, bb1 = r1 >> 11, t1 = r1 & (T_-1);
                size_t i0 = (((size_t)bb0*H_ + h)*T_ + t0)*D_;
                size_t i1 = (((size_t)bb1*H_ + h)*T_ + t1)*D_;
                float e00 = f2tf_f(acc[mt][nf][0] + b0);
                float e01 = f2tf_f(acc[mt][nf][1] + b1);
                float e10 = f2tf_f(acc[mt][nf][2] + b0);
                float e11 = f2tf_f(acc[mt][nf][3] + b1);
                if (sect == 1) {            // K: d-interleaved within 8-group
                    int db = dd & ~7;
                    dst[i0 + db + p0] = e00;  dst[i0 + db + p1] = e01;
                    dst[i1 + db + p0] = e10;  dst[i1 + db + p1] = e11;
                } else {                    // Q, V: plain
                    *(float2*)(dst + i0 + dd) = make_float2(e00, e01);
                    *(float2*)(dst + i1 + dd) = make_float2(e10, e11);
                }
            } else {         // final output: plain f32
                *(float2*)(out + (size_t)r0*C_ + col) =
                    make_float2(acc[mt][nf][0] + b0, acc[mt][nf][1] + b1);
                *(float2*)(out + (size_t)(r0+8)*C_ + col) =
                    make_float2(acc[mt][nf][2] + b0, acc[mt][nf][3] + b1);
            }
        }
    }
}

// ---------------------------------------------------------------------------
// Causal flash attention: 8 warps x 16 q-rows = 128-row block, 256 threads.
// g_k d-interleaved -> K fragments via LDS.64; P stored interleaved -> ap via
// LDS.64. 2-stage cp.async K/V ring; per-warp causal tile skip; exp2 softmax.
// ---------------------------------------------------------------------------
#define AK_LD 72
#define AV_LD 72
#define KS_SZ (64*AK_LD)
#define VS_SZ (64*AV_LD)
#define A_STAGE (KS_SZ + VS_SZ)
#define P_LD 72

__device__ __forceinline__ void attn_stage(float* sm, const float* Kg,
                                           const float* Vg, int kt, int tid)
{
    float* Ks = sm + (kt & 1) * A_STAGE;
    float* Vs = Ks + KS_SZ;
    const float* Kt = Kg + (size_t)(kt << 6) * D_;
    const float* Vt = Vg + (size_t)(kt << 6) * D_;
    const int r = tid >> 4, c = (tid & 15) << 2;
#pragma unroll
    for (int i = 0; i < 4; i++) {
        cp_async16(&Ks[(i*16 + r)*AK_LD + c], Kt + (i*16 + r)*D_ + c);
        cp_async16(&Vs[(i*16 + r)*AV_LD + c], Vt + (i*16 + r)*D_ + c);
    }
    CP_COMMIT();
}

__global__ __launch_bounds__(256, 2) void attn_mma()
{
    extern __shared__ float sm[];
    float* Ps = sm + 2*A_STAGE;          // per warp [16][P_LD]

    const int tid  = threadIdx.x;
    const int lane = tid & 31, w = tid >> 5;
    const int g = lane >> 2, ctg = lane & 3;
    const int qb = (gridDim.x - 1) - blockIdx.x;   // heavy blocks first
    const int bh = blockIdx.y;
    const int q0 = qb << 7;
    const int wq = q0 + (w << 4);                  // warp's 16 rows
    float* Pw = Ps + w * 16 * P_LD;

    const float* Qg = g_q + (size_t)bh * T_ * D_;
    const float* Kg = g_k + (size_t)bh * T_ * D_;
    const float* Vg = g_v + (size_t)bh * T_ * D_;

    // Q A-fragments; scale = 1/sqrt(64) * log2(e)  (exp2-domain softmax)
    const float qsc = 0.125f * 1.4426950408889634f;
    unsigned aq[8][4];
#pragma unroll
    for (int j = 0; j < 8; j++) {
        aq[j][0] = f2tf(Qg[(wq+g  )*D_ + (j<<3) + ctg    ] * qsc);
        aq[j][1] = f2tf(Qg[(wq+g+8)*D_ + (j<<3) + ctg    ] * qsc);
        aq[j][2] = f2tf(Qg[(wq+g  )*D_ + (j<<3) + ctg + 4] * qsc);
        aq[j][3] = f2tf(Qg[(wq+g+8)*D_ + (j<<3) + ctg + 4] * qsc);
    }

    float m_i[2] = {-1e30f, -1e30f};
    float l_i[2] = {0.f, 0.f};
    float o[8][4];
#pragma unroll
    for (int nf = 0; nf < 8; nf++)
#pragma unroll
        for (int r = 0; r < 4; r++) o[nf][r] = 0.f;

    const int p0 = ((ctg & 1) << 2) + (ctg >> 1), p1 = p0 + 2;

    const int nkt = (q0 >> 6) + 2;
    attn_stage(sm, Kg, Vg, 0, tid);

#pragma unroll 1
    for (int kt = 0; kt < nkt; kt++) {
        CP_WAIT(0);
        __syncthreads();
        if (kt + 1 < nkt) attn_stage(sm, Kg, Vg, kt + 1, tid);

        if ((kt << 6) <= wq + 15) {      // per-warp causal tile skip
            const float* Ksb = sm + (kt & 1) * A_STAGE;
            const float* Vsb = Ksb + KS_SZ;

            // S = Q K^T  (K interleaved -> LDS.64 fragment pairs)
            float s[8][4];
#pragma unroll
            for (int nf = 0; nf < 8; nf++)
#pragma unroll
                for (int r = 0; r < 4; r++) s[nf][r] = 0.f;
#pragma unroll
            for (int kk = 0; kk < 8; kk++) {
#pragma unroll
                for (int nf = 0; nf < 8; nf++) {
                    float2 bkv = *(const float2*)&Ksb[((nf<<3)+g)*AK_LD + (kk<<3) + (ctg<<1)];
                    unsigned bk[2] = { __float_as_uint(bkv.x), __float_as_uint(bkv.y) };
                    mma_tf32(s[nf], aq[kk], bk, s[nf]);
                }
            }

            // causal mask (diagonal-overlapping tiles only)
            if ((kt << 6) + 63 > wq) {
#pragma unroll
                for (int nf = 0; nf < 8; nf++) {
                    int col = (kt << 6) + (nf << 3) + (ctg << 1);
                    int r0 = wq + g, r1 = wq + g + 8;
                    if (col     > r0) s[nf][0] = -1e30f;
                    if (col + 1 > r0) s[nf][1] = -1e30f;
                    if (col     > r1) s[nf][2] = -1e30f;
                    if (col + 1 > r1) s[nf][3] = -1e30f;
                }
            }

            // online softmax (exp2 domain); a row lives on lanes 4g..4g+3
#pragma unroll
            for (int rr = 0; rr < 2; rr++) {
                float mx = -1e30f;
#pragma unroll
                for (int nf = 0; nf < 8; nf++)
                    mx = fmaxf(mx, fmaxf(s[nf][rr*2], s[nf][rr*2+1]));
                mx = fmaxf(mx, __shfl_xor_sync(0xffffffffu, mx, 1));
                mx = fmaxf(mx, __shfl_xor_sync(0xffffffffu, mx, 2));
                float mn = fmaxf(m_i[rr], mx);
                float alpha = exp2f(m_i[rr] - mn);
                m_i[rr] = mn;
                float rs = 0.f;
#pragma unroll
                for (int nf = 0; nf < 8; nf++) {
                    float pa = exp2f(s[nf][rr*2]   - mn);
                    float pb = exp2f(s[nf][rr*2+1] - mn);
                    s[nf][rr*2] = pa; s[nf][rr*2+1] = pb;
                    rs += pa + pb;
                }
                rs += __shfl_xor_sync(0xffffffffu, rs, 1);
                rs += __shfl_xor_sync(0xffffffffu, rs, 2);
                l_i[rr] = l_i[rr]*alpha + rs;
#pragma unroll
                for (int nf = 0; nf < 8; nf++) {
                    o[nf][rr*2]   *= alpha;
                    o[nf][rr*2+1] *= alpha;
                }
            }

            // P -> per-warp smem, interleaved within each 8-col group
#pragma unroll
            for (int nf = 0; nf < 8; nf++) {
                int cb = nf << 3;
                Pw[ g    *P_LD + cb + p0] = f2tf_f(s[nf][0]);
                Pw[ g    *P_LD + cb + p1] = f2tf_f(s[nf][1]);
                Pw[(g+8) *P_LD + cb + p0] = f2tf_f(s[nf][2]);
                Pw[(g+8) *P_LD + cb + p1] = f2tf_f(s[nf][3]);
            }
            __syncwarp();

            // O += P @ V  (P interleaved -> LDS.64 for ap)
#pragma unroll
            for (int kk = 0; kk < 8; kk++) {
                float2 a0 = *(const float2*)&Pw[ g    *P_LD + (kk<<3) + (ctg<<1)];
                float2 a1 = *(const float2*)&Pw[(g+8) *P_LD + (kk<<3) + (ctg<<1)];
                unsigned ap[4] = { __float_as_uint(a0.x), __float_as_uint(a1.x),
                                   __float_as_uint(a0.y), __float_as_uint(a1.y) };
#pragma unroll
                for (int nf = 0; nf < 8; nf++) {
                    unsigned bv[2];
                    bv[0] = __float_as_uint(Vsb[((kk<<3)+ctg  )*AV_LD + (nf<<3) + g]);
                    bv[1] = __float_as_uint(Vsb[((kk<<3)+ctg+4)*AV_LD + (nf<<3) + g]);
                    mma_tf32(o[nf], ap, bv, o[nf]);
                }
            }
        }
    }

    // epilogue: write [B*T, C] rounded + k-interleaved (packed proj input)
    const int b = bh >> 4, h = bh & 15;
    float inv0 = 1.0f / l_i[0], inv1 = 1.0f / l_i[1];
#pragma unroll
    for (int nf = 0; nf < 8; nf++) {
        size_t base0 = (size_t)(b*T_ + wq + g    )*C_ + (h << 6) + (nf << 3);
        size_t base1 = (size_t)(b*T_ + wq + g + 8)*C_ + (h << 6) + (nf << 3);
        g_ao[base0 + p0] = f2tf_f(o[nf][0]*inv0);
        g_ao[base0 + p1] = f2tf_f(o[nf][1]*inv0);
        g_ao[base1 + p0] = f2tf_f(o[nf][2]*inv1);
        g_ao[base1 + p1] = f2tf_f(o[nf][3]*inv1);
    }
}

// ---------------------------------------------------------------------------
extern "C" void kernel_launch(void* const* d_in, const int* in_sizes, int n_in,
                              void* d_out, int out_size)
{
    const float* x      = (const float*)d_in[0];
    const float* w_qkv  = (const float*)d_in[1];
    const float* b_qkv  = (const float*)d_in[2];
    const float* w_proj = (const float*)d_in[3];
    const float* b_proj = (const float*)d_in[4];
    float* out = (float*)d_out;

    float *x_p, *wq_p, *wp_p, *ao_p;
    cudaGetSymbolAddress((void**)&x_p,  g_x);
    cudaGetSymbolAddress((void**)&wq_p, g_wq);
    cudaGetSymbolAddress((void**)&wp_p, g_wp);
    cudaGetSymbolAddress((void**)&ao_p, g_ao);

    const int gemm_smem = 3 * G_STAGEW * (int)sizeof(float);              // 98304
    const int attn_smem = (2*A_STAGE + 8*16*P_LD) * (int)sizeof(float);   // 110592

    cudaFuncSetAttribute(mma_gemm<true>,
                         cudaFuncAttributeMaxDynamicSharedMemorySize, gemm_smem);
    cudaFuncSetAttribute(mma_gemm<false>,
                         cudaFuncAttributeMaxDynamicSharedMemorySize, gemm_smem);
    cudaFuncSetAttribute(attn_mma,
                         cudaFuncAttributeMaxDynamicSharedMemorySize, attn_smem);

    // prepack (one-time per call; memory-bound)
    pack_rows<<<M_*C_/8/256, 256>>>(x, x_p);
    pack_wt<<<dim3(3*C_/32, C_/32), dim3(32, 8)>>>(w_qkv, wq_p, 3*C_);
    pack_wt<<<dim3(C_/32, C_/32),   dim3(32, 8)>>>(w_proj, wp_p, C_);

    dim3 gq(24, 64);   // N=3072/128, M=8192/128
    mma_gemm<true><<<gq, 256, gemm_smem>>>(x_p, wq_p, b_qkv, nullptr);

    dim3 ga(16, 64);   // q-blocks (128 rows), B*H
    attn_mma<<<ga, 256, attn_smem>>>();

    dim3 gp(8, 64);    // N=1024/128, M=8192/128
    mma_gemm<false><<<gp, 256, gemm_smem>>>(ao_p, wp_p, b_proj, out);
}

// round 10
// speedup vs baseline: 1.7785x; 1.7785x over previous
#include <cuda_runtime.h>
#include <cuda_fp16.h>
#include <cstdint>

#define B_ 4
#define T_ 2048
#define C_ 1024
#define H_ 16
#define D_ 64
#define M_ (B_*T_)

// Scratch (device globals; allocation-free per harness rules)
__device__ __half g_x [M_*C_];        // x, fp16, k-pair-interleaved per 16
__device__ __half g_wq[3*C_*C_];      // w_qkv^T: [n][k], fp16, interleaved
__device__ __half g_wp[C_*C_];        // w_proj^T: [n][k], fp16, interleaved
__device__ __half g_q [B_*H_*T_*D_];  // [B,H,T,d], fp16 plain, qsc folded
__device__ __half g_k [B_*H_*T_*D_];  // [B,H,T,d], fp16, d-pair-interleaved
__device__ __half g_v [B_*H_*T_*D_];  // [B,H,T,d], fp16 plain
__device__ __half g_ao[M_*C_];        // attn out [B*T,C], fp16, interleaved

// ---------------------------------------------------------------------------
// helpers
// ---------------------------------------------------------------------------
__device__ __forceinline__ void mma_f16(float* d, const unsigned* a,
                                        const unsigned* b, const float* c) {
    asm volatile(
        "mma.sync.aligned.m16n8k16.row.col.f32.f16.f16.f32 "
        "{%0,%1,%2,%3}, {%4,%5,%6,%7}, {%8,%9}, {%10,%11,%12,%13};\n"
        : "=f"(d[0]), "=f"(d[1]), "=f"(d[2]), "=f"(d[3])
        : "r"(a[0]), "r"(a[1]), "r"(a[2]), "r"(a[3]),
          "r"(b[0]), "r"(b[1]),
          "f"(c[0]), "f"(c[1]), "f"(c[2]), "f"(c[3]));
}
__device__ __forceinline__ void ldsm_x4_t(unsigned& r0, unsigned& r1,
                                          unsigned& r2, unsigned& r3,
                                          unsigned addr) {
    asm volatile("ldmatrix.sync.aligned.m8n8.x4.trans.shared.b16 "
                 "{%0,%1,%2,%3}, [%4];"
                 : "=r"(r0), "=r"(r1), "=r"(r2), "=r"(r3) : "r"(addr));
}
__device__ __forceinline__ void cp_async16(void* smem, const void* gmem) {
    unsigned saddr = (unsigned)__cvta_generic_to_shared(smem);
    asm volatile("cp.async.cg.shared.global [%0], [%1], 16;\n"
                 :: "r"(saddr), "l"(gmem) : "memory");
}
#define CP_COMMIT() asm volatile("cp.async.commit_group;\n" ::: "memory")
#define CP_WAIT(n)  asm volatile("cp.async.wait_group %0;\n" :: "n"(n) : "memory")

// attention softmax scale folded into Q at QKV epilogue: 1/sqrt(64)*log2(e)
#define QSC (0.125f * 1.4426950408889634f)

// ---------------------------------------------------------------------------
// Prepack: fp16 + pair-interleave per 16-group (pairs p<4 -> slot 2p,
// p>=4 -> slot 2(p-4)+1), making fragment pairs (k,k+8) adjacent -> LDS.64.
// ---------------------------------------------------------------------------
__device__ __constant__ int c_P8[8] = {0, 4, 1, 5, 2, 6, 3, 7};

__global__ __launch_bounds__(256) void pack_rows_h(const float* __restrict__ in,
                                                   __half* __restrict__ out)
{
    size_t gid = (size_t)blockIdx.x * 256 + threadIdx.x;   // one 16-group
    float f[16];
#pragma unroll
    for (int i = 0; i < 4; i++)
        *(float4*)&f[i*4] = *(const float4*)(in + gid*16 + i*4);
    __half h[16];
#pragma unroll
    for (int s = 0; s < 8; s++) {
        int p = c_P8[s];
        h[2*s]   = __float2half_rn(f[2*p]);
        h[2*s+1] = __float2half_rn(f[2*p+1]);
    }
    *(uint4*)(out + gid*16)     = *(uint4*)&h[0];
    *(uint4*)(out + gid*16 + 8) = *(uint4*)&h[8];
}

// W [K=1024][N] row-major -> out [N][1024] transposed + fp16 + interleaved
__global__ __launch_bounds__(256) void pack_wt_h(const float* __restrict__ W,
                                                 __half* __restrict__ out, int N)
{
    __shared__ float t[32][33];
    const int n0 = blockIdx.x << 5, k0 = blockIdx.y << 5;
    const int tx = threadIdx.x, ty = threadIdx.y;          // 32 x 8
#pragma unroll
    for (int i = ty; i < 32; i += 8)
        t[i][tx] = W[(size_t)(k0 + i) * N + n0 + tx];
    __syncthreads();
    const int grp = tx >> 4, j16 = tx & 15;
    const int p = j16 >> 1, bit = j16 & 1;
    const int slot = (p < 4) ? (p << 1) : (((p - 4) << 1) + 1);
    const int kp = (grp << 4) + (slot << 1) + bit;
#pragma unroll
    for (int i = ty; i < 32; i += 8)
        out[(size_t)(n0 + i) * C_ + k0 + kp] = __float2half_rn(t[tx][i]);
}

// ---------------------------------------------------------------------------
// GEMM: 128x128 block, 8 warps (4x2 of 32x64 warp tiles), 256 threads.
// fp16 m16n8k16. K-step 64 (rows = 128B), XOR swizzle (off ^ (row&3)<<5),
// 3-stage cp.async ring. Per K-step: 4 chunks x (12 LDS.64 + 16 MMA).
// ---------------------------------------------------------------------------
#define G_TILEB 16384                  // 128 rows x 128 B
#define G_STGB  (2*G_TILEB)
#define NKS 16                         // 1024 / 64

__device__ __forceinline__ void gemm_stage(char* smc, const __half* A,
    const __half* B, int m0, int n0, int ks, int st, int tid)
{
    char* As = smc + st * G_STGB;
    char* Bs = As + G_TILEB;
    const int k0 = ks << 6;
    const int r = tid >> 3, c16 = tid & 7;
    const int swo = (c16 * 16) ^ ((r & 3) << 5);
#pragma unroll
    for (int i = 0; i < 4; i++) {
        int row = i*32 + r;                       // row&3 == r&3
        cp_async16(As + row*128 + swo, A + (size_t)(m0 + row)*C_ + k0 + c16*8);
        cp_async16(Bs + row*128 + swo, B + (size_t)(n0 + row)*C_ + k0 + c16*8);
    }
    CP_COMMIT();
}

template<bool SCATTER>
__global__ __launch_bounds__(256, 2) void mma_gemm(
    const __half* __restrict__ Ap, const __half* __restrict__ Bp,
    const float* __restrict__ bias, float* __restrict__ out)
{
    extern __shared__ char smc[];

    const int tid  = threadIdx.x;
    const int lane = tid & 31, w = tid >> 5;
    const int g = lane >> 2, ctg = lane & 3;
    const int wm = (w >> 1) << 5;     // 0,32,64,96
    const int wn = (w & 1)  << 6;     // 0,64
    const int m0 = blockIdx.y << 7, n0 = blockIdx.x << 7;

    float acc[2][8][4];
#pragma unroll
    for (int mt = 0; mt < 2; mt++)
#pragma unroll
        for (int nf = 0; nf < 8; nf++)
#pragma unroll
            for (int r = 0; r < 4; r++) acc[mt][nf][r] = 0.f;

    gemm_stage(smc, Ap, Bp, m0, n0, 0, 0, tid);
    gemm_stage(smc, Ap, Bp, m0, n0, 1, 1, tid);

#pragma unroll 1
    for (int ks = 0; ks < NKS; ks++) {
        if (ks + 1 < NKS) { CP_WAIT(1); } else { CP_WAIT(0); }
        __syncthreads();
        if (ks + 2 < NKS)
            gemm_stage(smc, Ap, Bp, m0, n0, ks + 2, (ks + 2) % 3, tid);

        const char* As = smc + (ks % 3) * G_STGB;
        const char* Bs = As + G_TILEB;
#pragma unroll
        for (int c = 0; c < 4; c++) {
            const int coff = ((32*c) ^ ((g & 3) << 5)) + 8*ctg;
            unsigned afr[2][4];
#pragma unroll
            for (int mt = 0; mt < 2; mt++) {
                int rb = wm + (mt << 4) + g;
                uint2 va = *(const uint2*)(As + rb*128 + coff);
                uint2 vb = *(const uint2*)(As + (rb+8)*128 + coff);
                afr[mt][0] = va.x; afr[mt][2] = va.y;
                afr[mt][1] = vb.x; afr[mt][3] = vb.y;
            }
#pragma unroll
            for (int nf = 0; nf < 8; nf++) {
                uint2 bv = *(const uint2*)(Bs + (wn + nf*8 + g)*128 + coff);
                unsigned bfr[2] = { bv.x, bv.y };
                mma_f16(acc[0][nf], afr[0], bfr, acc[0][nf]);
                mma_f16(acc[1][nf], afr[1], bfr, acc[1][nf]);
            }
        }
    }

    // Epilogue
#pragma unroll
    for (int mt = 0; mt < 2; mt++) {
#pragma unroll
        for (int nf = 0; nf < 8; nf++) {
            int col = n0 + wn + (nf << 3) + (ctg << 1);
            int r0  = m0 + wm + (mt << 4) + g;
            float b0 = bias[col], b1 = bias[col + 1];
            float e00 = acc[mt][nf][0] + b0, e01 = acc[mt][nf][1] + b1;
            float e10 = acc[mt][nf][2] + b0, e11 = acc[mt][nf][3] + b1;
            if (SCATTER) {   // qkv -> g_q/g_k/g_v (fp16)
                int sect = col >> 10, cc = col & 1023;
                int h = cc >> 6, dd = cc & 63;
                __half* dst = (sect == 0) ? g_q : (sect == 1) ? g_k : g_v;
                int bb0 = r0 >> 11, t0 = r0 & (T_-1);
                int r1 = r0 + 8, bb1 = r1 >> 11, t1 = r1 & (T_-1);
                size_t i0 = (((size_t)bb0*H_ + h)*T_ + t0)*D_;
                size_t i1 = (((size_t)bb1*H_ + h)*T_ + t1)*D_;
                if (sect == 0) {          // Q: plain, softmax scale folded
                    *(__half2*)(dst + i0 + dd) = __floats2half2_rn(e00*QSC, e01*QSC);
                    *(__half2*)(dst + i1 + dd) = __floats2half2_rn(e10*QSC, e11*QSC);
                } else if (sect == 1) {   // K: d-pair-interleaved per 16
                    int off = (dd & ~15) + 4*ctg + 2*(nf & 1);
                    *(__half2*)(dst + i0 + off) = __floats2half2_rn(e00, e01);
                    *(__half2*)(dst + i1 + off) = __floats2half2_rn(e10, e11);
                } else {                  // V: plain
                    *(__half2*)(dst + i0 + dd) = __floats2half2_rn(e00, e01);
                    *(__half2*)(dst + i1 + dd) = __floats2half2_rn(e10, e11);
                }
            } else {         // final output: plain f32
                *(float2*)(out + (size_t)r0*C_ + col) = make_float2(e00, e01);
                *(float2*)(out + (size_t)(r0+8)*C_ + col) = make_float2(e10, e11);
            }
        }
    }
}

// ---------------------------------------------------------------------------
// Causal flash attention (fp16 m16n8k16): 8 warps x 16 q-rows, 256 threads.
// K smem [64][80 halves] (pair-interleaved), V smem [64][72 halves] plain
// (ldmatrix.x4.trans for B-frags), P per-warp [16][80 halves] interleaved.
// 3-stage cp.async K/V ring; per-warp causal tile skip; exp2 softmax.
// ---------------------------------------------------------------------------
#define AK_B 160        // K row stride bytes (80 halves): 160 % 128 = 32
#define AV_B 144        // V row stride bytes (72 halves): 144 % 128 = 16
#define KS_B (64*AK_B)  // 10240
#define VS_B (64*AV_B)  //  9216
#define A_STGB (KS_B + VS_B)
#define P_B 160

__device__ __forceinline__ void attn_stage(char* smc, const __half* Kg,
                                           const __half* Vg, int kt, int tid)
{
    char* Ks = smc + (kt % 3) * A_STGB;
    char* Vs = Ks + KS_B;
    const __half* Kt = Kg + (size_t)(kt << 6) * D_;
    const __half* Vt = Vg + (size_t)(kt << 6) * D_;
    const int r = tid >> 3, c16 = tid & 7;
#pragma unroll
    for (int i = 0; i < 2; i++) {
        int row = i*32 + r;
        cp_async16(Ks + row*AK_B + c16*16, Kt + row*D_ + c16*8);
        cp_async16(Vs + row*AV_B + c16*16, Vt + row*D_ + c16*8);
    }
    CP_COMMIT();
}

__global__ __launch_bounds__(256, 2) void attn_mma()
{
    extern __shared__ char smc[];
    char* Ps = smc + 3*A_STGB;           // per warp [16][P_B bytes]

    const int tid  = threadIdx.x;
    const int lane = tid & 31, w = tid >> 5;
    const int g = lane >> 2, ctg = lane & 3;
    const int qb = (gridDim.x - 1) - blockIdx.x;   // heavy blocks first
    const int bh = blockIdx.y;
    const int q0 = qb << 7;
    const int wq = q0 + (w << 4);                  // warp's 16 rows
    char* Pw = Ps + w * 16 * P_B;

    const __half* Qg = g_q + (size_t)bh * T_ * D_;
    const __half* Kg = g_k + (size_t)bh * T_ * D_;
    const __half* Vg = g_v + (size_t)bh * T_ * D_;

    // Q A-fragments (scale already folded into g_q): 4 chunks of K=16
    unsigned aq[4][4];
#pragma unroll
    for (int j = 0; j < 4; j++) {
        const __half* q0p = Qg + (size_t)(wq + g)*D_ + 16*j + 2*ctg;
        const __half* q1p = Qg + (size_t)(wq + g + 8)*D_ + 16*j + 2*ctg;
        aq[j][0] = *(const unsigned*)(q0p);
        aq[j][2] = *(const unsigned*)(q0p + 8);
        aq[j][1] = *(const unsigned*)(q1p);
        aq[j][3] = *(const unsigned*)(q1p + 8);
    }

    float m_i[2] = {-1e30f, -1e30f};
    float l_i[2] = {0.f, 0.f};
    float o[8][4];
#pragma unroll
    for (int nf = 0; nf < 8; nf++)
#pragma unroll
        for (int r = 0; r < 4; r++) o[nf][r] = 0.f;

    // ldmatrix per-lane address components (V b-frags)
    const int tix = lane >> 3;
    const int ldm_row = (lane & 7) + ((tix & 1) << 3);
    const int ldm_col = (tix >> 1) << 4;           // bytes

    const int nkt = (q0 >> 6) + 2;
    attn_stage(smc, Kg, Vg, 0, tid);
    attn_stage(smc, Kg, Vg, 1, tid);

#pragma unroll 1
    for (int kt = 0; kt < nkt; kt++) {
        if (kt + 1 < nkt) { CP_WAIT(1); } else { CP_WAIT(0); }
        __syncthreads();
        if (kt + 2 < nkt) attn_stage(smc, Kg, Vg, kt + 2, tid);

        if ((kt << 6) <= wq + 15) {      // per-warp causal tile skip
            const char* Ksb = smc + (kt % 3) * A_STGB;
            const char* Vsb = Ksb + KS_B;
            const unsigned vbase = (unsigned)__cvta_generic_to_shared(Vsb);

            // S = Q K^T  (K pair-interleaved -> LDS.64 b-frags)
            float s[8][4];
#pragma unroll
            for (int nf = 0; nf < 8; nf++)
#pragma unroll
                for (int r = 0; r < 4; r++) s[nf][r] = 0.f;
#pragma unroll
            for (int j = 0; j < 4; j++) {
#pragma unroll
                for (int nf = 0; nf < 8; nf++) {
                    uint2 bk = *(const uint2*)(Ksb + (nf*8 + g)*AK_B + 32*j + 8*ctg);
                    unsigned bfr[2] = { bk.x, bk.y };
                    mma_f16(s[nf], aq[j], bfr, s[nf]);
                }
            }

            // causal mask (diagonal-overlapping tiles only)
            if ((kt << 6) + 63 > wq) {
#pragma unroll
                for (int nf = 0; nf < 8; nf++) {
                    int col = (kt << 6) + (nf << 3) + (ctg << 1);
                    int r0 = wq + g, r1 = wq + g + 8;
                    if (col     > r0) s[nf][0] = -1e30f;
                    if (col + 1 > r0) s[nf][1] = -1e30f;
                    if (col     > r1) s[nf][2] = -1e30f;
                    if (col + 1 > r1) s[nf][3] = -1e30f;
                }
            }

            // online softmax (exp2 domain); a row lives on lanes 4g..4g+3
#pragma unroll
            for (int rr = 0; rr < 2; rr++) {
                float mx = -1e30f;
#pragma unroll
                for (int nf = 0; nf < 8; nf++)
                    mx = fmaxf(mx, fmaxf(s[nf][rr*2], s[nf][rr*2+1]));
                mx = fmaxf(mx, __shfl_xor_sync(0xffffffffu, mx, 1));
                mx = fmaxf(mx, __shfl_xor_sync(0xffffffffu, mx, 2));
                float mn = fmaxf(m_i[rr], mx);
                float alpha = exp2f(m_i[rr] - mn);
                m_i[rr] = mn;
                float rs = 0.f;
#pragma unroll
                for (int nf = 0; nf < 8; nf++) {
                    float pa = exp2f(s[nf][rr*2]   - mn);
                    float pb = exp2f(s[nf][rr*2+1] - mn);
                    s[nf][rr*2] = pa; s[nf][rr*2+1] = pb;
                    rs += pa + pb;
                }
                rs += __shfl_xor_sync(0xffffffffu, rs, 1);
                rs += __shfl_xor_sync(0xffffffffu, rs, 2);
                l_i[rr] = l_i[rr]*alpha + rs;
#pragma unroll
                for (int nf = 0; nf < 8; nf++) {
                    o[nf][rr*2]   *= alpha;
                    o[nf][rr*2+1] *= alpha;
                }
            }

            // P -> per-warp smem (fp16, pair-interleaved)
#pragma unroll
            for (int nf = 0; nf < 8; nf++) {
                int off = (nf >> 1)*32 + 8*ctg + 4*(nf & 1);
                *(__half2*)(Pw + g*P_B + off) =
                    __floats2half2_rn(s[nf][0], s[nf][1]);
                *(__half2*)(Pw + (g+8)*P_B + off) =
                    __floats2half2_rn(s[nf][2], s[nf][3]);
            }
            __syncwarp();

            // O += P @ V  (P -> LDS.64 a-frags; V -> ldmatrix.x4.trans)
#pragma unroll
            for (int j = 0; j < 4; j++) {
                uint2 pa = *(const uint2*)(Pw + g*P_B + 32*j + 8*ctg);
                uint2 pb = *(const uint2*)(Pw + (g+8)*P_B + 32*j + 8*ctg);
                unsigned ap[4] = { pa.x, pb.x, pa.y, pb.y };
#pragma unroll
                for (int nfp = 0; nfp < 8; nfp += 2) {
                    unsigned r0, r1, r2, r3;
                    unsigned addr = vbase + (16*j + ldm_row)*AV_B + nfp*16 + ldm_col;
                    ldsm_x4_t(r0, r1, r2, r3, addr);
                    unsigned b0[2] = { r0, r1 };
                    unsigned b1[2] = { r2, r3 };
                    mma_f16(o[nfp],   ap, b0, o[nfp]);
                    mma_f16(o[nfp+1], ap, b1, o[nfp+1]);
                }
            }
        }
    }

    // epilogue: write g_ao fp16, pair-interleaved (packed proj input)
    const int b = bh >> 4, h = bh & 15;
    float inv0 = 1.0f / l_i[0], inv1 = 1.0f / l_i[1];
#pragma unroll
    for (int nf = 0; nf < 8; nf++) {
        int off = (h << 6) + (nf >> 1)*16 + 4*ctg + 2*(nf & 1);
        size_t base0 = (size_t)(b*T_ + wq + g    )*C_ + off;
        size_t base1 = (size_t)(b*T_ + wq + g + 8)*C_ + off;
        *(__half2*)(g_ao + base0) = __floats2half2_rn(o[nf][0]*inv0, o[nf][1]*inv0);
        *(__half2*)(g_ao + base1) = __floats2half2_rn(o[nf][2]*inv1, o[nf][3]*inv1);
    }
}

// ---------------------------------------------------------------------------
extern "C" void kernel_launch(void* const* d_in, const int* in_sizes, int n_in,
                              void* d_out, int out_size)
{
    const float* x      = (const float*)d_in[0];
    const float* w_qkv  = (const float*)d_in[1];
    const float* b_qkv  = (const float*)d_in[2];
    const float* w_proj = (const float*)d_in[3];
    const float* b_proj = (const float*)d_in[4];
    float* out = (float*)d_out;

    __half *x_p, *wq_p, *wp_p, *ao_p;
    cudaGetSymbolAddress((void**)&x_p,  g_x);
    cudaGetSymbolAddress((void**)&wq_p, g_wq);
    cudaGetSymbolAddress((void**)&wp_p, g_wp);
    cudaGetSymbolAddress((void**)&ao_p, g_ao);

    const int gemm_smem = 3 * G_STGB;                       // 98304
    const int attn_smem = 3 * A_STGB + 8 * 16 * P_B;        // 78848

    cudaFuncSetAttribute(mma_gemm<true>,
                         cudaFuncAttributeMaxDynamicSharedMemorySize, gemm_smem);
    cudaFuncSetAttribute(mma_gemm<false>,
                         cudaFuncAttributeMaxDynamicSharedMemorySize, gemm_smem);
    cudaFuncSetAttribute(attn_mma,
                         cudaFuncAttributeMaxDynamicSharedMemorySize, attn_smem);

    // prepack (one-time per call; memory-bound)
    pack_rows_h<<<M_*C_/16/256, 256>>>(x, x_p);
    pack_wt_h<<<dim3(3*C_/32, C_/32), dim3(32, 8)>>>(w_qkv, wq_p, 3*C_);
    pack_wt_h<<<dim3(C_/32, C_/32),   dim3(32, 8)>>>(w_proj, wp_p, C_);

    dim3 gq(24, 64);   // N=3072/128, M=8192/128
    mma_gemm<true><<<gq, 256, gemm_smem>>>(x_p, wq_p, b_qkv, nullptr);

    dim3 ga(16, 64);   // q-blocks (128 rows), B*H
    attn_mma<<<ga, 256, attn_smem>>>();

    dim3 gp(8, 64);    // N=1024/128, M=8192/128
    mma_gemm<false><<<gp, 256, gemm_smem>>>(ao_p, wp_p, b_proj, out);
}

// round 11
// speedup vs baseline: 1.9512x; 1.0971x over previous
#include <cuda_runtime.h>
#include <cuda_fp16.h>
#include <cstdint>

#define B_ 4
#define T_ 2048
#define C_ 1024
#define H_ 16
#define D_ 64
#define M_ (B_*T_)

// Scratch (device globals; allocation-free per harness rules) — all PLAIN fp16
__device__ __half g_x [M_*C_];        // x [m][k]
__device__ __half g_wq[3*C_*C_];      // w_qkv^T [n][k]
__device__ __half g_wp[C_*C_];        // w_proj^T [n][k]
__device__ __half g_q [B_*H_*T_*D_];  // [B,H,T,d], qsc folded
__device__ __half g_k [B_*H_*T_*D_];  // [B,H,T,d]
__device__ __half g_v [B_*H_*T_*D_];  // [B,H,T,d]
__device__ __half g_ao[M_*C_];        // attn out [B*T,C]

// ---------------------------------------------------------------------------
// helpers
// ---------------------------------------------------------------------------
__device__ __forceinline__ void mma_f16(float* d, const unsigned* a,
                                        const unsigned* b, const float* c) {
    asm volatile(
        "mma.sync.aligned.m16n8k16.row.col.f32.f16.f16.f32 "
        "{%0,%1,%2,%3}, {%4,%5,%6,%7}, {%8,%9}, {%10,%11,%12,%13};\n"
        : "=f"(d[0]), "=f"(d[1]), "=f"(d[2]), "=f"(d[3])
        : "r"(a[0]), "r"(a[1]), "r"(a[2]), "r"(a[3]),
          "r"(b[0]), "r"(b[1]),
          "f"(c[0]), "f"(c[1]), "f"(c[2]), "f"(c[3]));
}
__device__ __forceinline__ void ldsm_x4(unsigned& r0, unsigned& r1,
                                        unsigned& r2, unsigned& r3,
                                        unsigned addr) {
    asm volatile("ldmatrix.sync.aligned.m8n8.x4.shared.b16 "
                 "{%0,%1,%2,%3}, [%4];"
                 : "=r"(r0), "=r"(r1), "=r"(r2), "=r"(r3) : "r"(addr));
}
__device__ __forceinline__ void ldsm_x4_t(unsigned& r0, unsigned& r1,
                                          unsigned& r2, unsigned& r3,
                                          unsigned addr) {
    asm volatile("ldmatrix.sync.aligned.m8n8.x4.trans.shared.b16 "
                 "{%0,%1,%2,%3}, [%4];"
                 : "=r"(r0), "=r"(r1), "=r"(r2), "=r"(r3) : "r"(addr));
}
__device__ __forceinline__ void cp_async16(void* smem, const void* gmem) {
    unsigned saddr = (unsigned)__cvta_generic_to_shared(smem);
    asm volatile("cp.async.cg.shared.global [%0], [%1], 16;\n"
                 :: "r"(saddr), "l"(gmem) : "memory");
}
#define CP_COMMIT() asm volatile("cp.async.commit_group;\n" ::: "memory")
#define CP_WAIT(n)  asm volatile("cp.async.wait_group %0;\n" :: "n"(n) : "memory")

// attention softmax scale folded into Q at QKV epilogue: 1/sqrt(64)*log2(e)
#define QSC (0.125f * 1.4426950408889634f)

// ---------------------------------------------------------------------------
// Prepack: plain fp16 convert (rows), transpose+convert (weights).
// ---------------------------------------------------------------------------
__global__ __launch_bounds__(256) void pack_rows_h(const float* __restrict__ in,
                                                   __half* __restrict__ out)
{
    size_t gid = (size_t)blockIdx.x * 256 + threadIdx.x;   // one 16-group
    __half h[16];
#pragma unroll
    for (int i = 0; i < 4; i++) {
        float4 f = *(const float4*)(in + gid*16 + i*4);
        h[i*4+0] = __float2half_rn(f.x); h[i*4+1] = __float2half_rn(f.y);
        h[i*4+2] = __float2half_rn(f.z); h[i*4+3] = __float2half_rn(f.w);
    }
    *(uint4*)(out + gid*16)     = *(uint4*)&h[0];
    *(uint4*)(out + gid*16 + 8) = *(uint4*)&h[8];
}

// W [K=1024][N] row-major -> out [N][1024] transposed + fp16
__global__ __launch_bounds__(256) void pack_wt_h(const float* __restrict__ W,
                                                 __half* __restrict__ out, int N)
{
    __shared__ float t[32][33];
    const int n0 = blockIdx.x << 5, k0 = blockIdx.y << 5;
    const int tx = threadIdx.x, ty = threadIdx.y;          // 32 x 8
#pragma unroll
    for (int i = ty; i < 32; i += 8)
        t[i][tx] = W[(size_t)(k0 + i) * N + n0 + tx];
    __syncthreads();
#pragma unroll
    for (int i = ty; i < 32; i += 8)
        out[(size_t)(n0 + i) * C_ + k0 + tx] = __float2half_rn(t[tx][i]);
}

// ---------------------------------------------------------------------------
// GEMM: 128x128 block, 8 warps (4x2 of 32x64 warp tiles), 256 threads.
// fp16 m16n8k16 via ldmatrix.x4 A/B fragments. K-step 64 (row = 128B),
// XOR swizzle: 16B chunk col ^ ((row&7)<<4) -> conflict-free ldmatrix.
// 3-stage cp.async ring.
// ---------------------------------------------------------------------------
#define G_TILEB 16384                  // 128 rows x 128 B
#define G_STGB  (2*G_TILEB)
#define NKS 16                         // 1024 / 64

__device__ __forceinline__ void gemm_stage(char* smc, const __half* A,
    const __half* B, int m0, int n0, int ks, int st, int tid)
{
    char* As = smc + st * G_STGB;
    char* Bs = As + G_TILEB;
    const int k0 = ks << 6;
    const int r = tid >> 3, c16 = tid & 7;
    const int swo = (c16 * 16) ^ ((r & 7) << 4);
#pragma unroll
    for (int i = 0; i < 4; i++) {
        int row = i*32 + r;                       // row&7 == r&7
        cp_async16(As + row*128 + swo, A + (size_t)(m0 + row)*C_ + k0 + c16*8);
        cp_async16(Bs + row*128 + swo, B + (size_t)(n0 + row)*C_ + k0 + c16*8);
    }
    CP_COMMIT();
}

template<bool SCATTER>
__global__ __launch_bounds__(256, 2) void mma_gemm(
    const __half* __restrict__ Ap, const __half* __restrict__ Bp,
    const float* __restrict__ bias, float* __restrict__ out)
{
    extern __shared__ char smc[];
    const unsigned su = (unsigned)__cvta_generic_to_shared(smc);

    const int tid  = threadIdx.x;
    const int lane = tid & 31, w = tid >> 5;
    const int g = lane >> 2, ctg = lane & 3;
    const int wm = (w >> 1) << 5;     // 0,32,64,96
    const int wn = (w & 1)  << 6;     // 0,64
    const int m0 = blockIdx.y << 7, n0 = blockIdx.x << 7;

    // ldmatrix lane roles
    const int lrow_a = lane & 15,  kh_a = lane >> 4;          // A quadrants
    const int lrow_b = (lane & 7) | ((lane >> 4) << 3);       // B quadrants
    const int kh_b   = (lane >> 3) & 1;
    const unsigned amask = (unsigned)((lrow_a & 7) << 4);
    const unsigned bmask = (unsigned)((lrow_b & 7) << 4);

    float acc[2][8][4];
#pragma unroll
    for (int mt = 0; mt < 2; mt++)
#pragma unroll
        for (int nf = 0; nf < 8; nf++)
#pragma unroll
            for (int r = 0; r < 4; r++) acc[mt][nf][r] = 0.f;

    gemm_stage(smc, Ap, Bp, m0, n0, 0, 0, tid);
    gemm_stage(smc, Ap, Bp, m0, n0, 1, 1, tid);

#pragma unroll 1
    for (int ks = 0; ks < NKS; ks++) {
        if (ks + 1 < NKS) { CP_WAIT(1); } else { CP_WAIT(0); }
        __syncthreads();
        if (ks + 2 < NKS)
            gemm_stage(smc, Ap, Bp, m0, n0, ks + 2, (ks + 2) % 3, tid);

        const unsigned ast = su + (ks % 3) * G_STGB;
        const unsigned bst = ast + G_TILEB;
        const unsigned aRow0 = ast + (wm + lrow_a) * 128;          // mt=0
        const unsigned aRow1 = aRow0 + 16 * 128;                   // mt=1
        const unsigned bRowBase = bst + (wn + lrow_b) * 128;
#pragma unroll
        for (int c = 0; c < 4; c++) {
            const unsigned acol = (unsigned)(32*c + kh_a*16) ^ amask;
            const unsigned bcol = (unsigned)(32*c + kh_b*16) ^ bmask;
            unsigned afr[2][4];
            ldsm_x4(afr[0][0], afr[0][1], afr[0][2], afr[0][3], aRow0 + acol);
            ldsm_x4(afr[1][0], afr[1][1], afr[1][2], afr[1][3], aRow1 + acol);
#pragma unroll
            for (int p = 0; p < 4; p++) {
                unsigned q0, q1, q2, q3;
                ldsm_x4(q0, q1, q2, q3, bRowBase + (unsigned)(p*16*128) + bcol);
                unsigned b0[2] = { q0, q1 };
                unsigned b1[2] = { q2, q3 };
                mma_f16(acc[0][2*p],   afr[0], b0, acc[0][2*p]);
                mma_f16(acc[1][2*p],   afr[1], b0, acc[1][2*p]);
                mma_f16(acc[0][2*p+1], afr[0], b1, acc[0][2*p+1]);
                mma_f16(acc[1][2*p+1], afr[1], b1, acc[1][2*p+1]);
            }
        }
    }

    // Epilogue
#pragma unroll
    for (int mt = 0; mt < 2; mt++) {
#pragma unroll
        for (int nf = 0; nf < 8; nf++) {
            int col = n0 + wn + (nf << 3) + (ctg << 1);
            int r0  = m0 + wm + (mt << 4) + g;
            float b0 = bias[col], b1 = bias[col + 1];
            float e00 = acc[mt][nf][0] + b0, e01 = acc[mt][nf][1] + b1;
            float e10 = acc[mt][nf][2] + b0, e11 = acc[mt][nf][3] + b1;
            if (SCATTER) {   // qkv -> g_q/g_k/g_v (fp16, plain)
                int sect = col >> 10, cc = col & 1023;
                int h = cc >> 6, dd = cc & 63;
                __half* dst = (sect == 0) ? g_q : (sect == 1) ? g_k : g_v;
                int bb0 = r0 >> 11, t0 = r0 & (T_-1);
                int r1 = r0 + 8, bb1 = r1 >> 11, t1 = r1 & (T_-1);
                size_t i0 = (((size_t)bb0*H_ + h)*T_ + t0)*D_ + dd;
                size_t i1 = (((size_t)bb1*H_ + h)*T_ + t1)*D_ + dd;
                if (sect == 0) {          // Q: softmax scale folded
                    *(__half2*)(dst + i0) = __floats2half2_rn(e00*QSC, e01*QSC);
                    *(__half2*)(dst + i1) = __floats2half2_rn(e10*QSC, e11*QSC);
                } else {
                    *(__half2*)(dst + i0) = __floats2half2_rn(e00, e01);
                    *(__half2*)(dst + i1) = __floats2half2_rn(e10, e11);
                }
            } else {         // final output: plain f32
                *(float2*)(out + (size_t)r0*C_ + col) = make_float2(e00, e01);
                *(float2*)(out + (size_t)(r0+8)*C_ + col) = make_float2(e10, e11);
            }
        }
    }
}

// ---------------------------------------------------------------------------
// Causal flash attention (fp16): 8 warps x 16 q-rows, 256 threads.
// K/V/P all plain, pad-144 rows (conflict-free ldmatrix: banks 4r mod 32).
// S B-frags + PV A-frags via ldmatrix.x4; V via ldmatrix.x4.trans.
// 3-stage cp.async K/V ring; per-warp causal tile skip; exp2 softmax.
// ---------------------------------------------------------------------------
#define AK_B 144        // K row stride bytes (64 halves data + pad)
#define AV_B 144
#define P_B  144
#define KS_B (64*AK_B)
#define VS_B (64*AV_B)
#define A_STGB (KS_B + VS_B)

__device__ __forceinline__ void attn_stage(char* smc, const __half* Kg,
                                           const __half* Vg, int kt, int tid)
{
    char* Ks = smc + (kt % 3) * A_STGB;
    char* Vs = Ks + KS_B;
    const __half* Kt = Kg + (size_t)(kt << 6) * D_;
    const __half* Vt = Vg + (size_t)(kt << 6) * D_;
    const int r = tid >> 3, c16 = tid & 7;
#pragma unroll
    for (int i = 0; i < 2; i++) {
        int row = i*32 + r;
        cp_async16(Ks + row*AK_B + c16*16, Kt + row*D_ + c16*8);
        cp_async16(Vs + row*AV_B + c16*16, Vt + row*D_ + c16*8);
    }
    CP_COMMIT();
}

__global__ __launch_bounds__(256, 2) void attn_mma()
{
    extern __shared__ char smc[];
    char* Ps = smc + 3*A_STGB;           // per warp [16][P_B bytes]

    const int tid  = threadIdx.x;
    const int lane = tid & 31, w = tid >> 5;
    const int g = lane >> 2, ctg = lane & 3;
    const int qb = (gridDim.x - 1) - blockIdx.x;   // heavy blocks first
    const int bh = blockIdx.y;
    const int q0 = qb << 7;
    const int wq = q0 + (w << 4);                  // warp's 16 rows
    char* Pw = Ps + w * 16 * P_B;
    const unsigned pw_u = (unsigned)__cvta_generic_to_shared(Pw);

    const __half* Qg = g_q + (size_t)bh * T_ * D_;
    const __half* Kg = g_k + (size_t)bh * T_ * D_;
    const __half* Vg = g_v + (size_t)bh * T_ * D_;

    // ldmatrix lane roles
    const int lrow_a = lane & 15,  kh_a = lane >> 4;          // A / P
    const int lrow_b = (lane & 7) | ((lane >> 4) << 3);       // K (B-side)
    const int kh_b   = (lane >> 3) & 1;
    const int tix = lane >> 3;                                 // V (trans)
    const int ldm_row = (lane & 7) + ((tix & 1) << 3);
    const int ldm_col = (tix >> 1) << 4;

    // Q A-fragments (scale folded): 4 chunks of K=16, direct gmem loads
    unsigned aq[4][4];
#pragma unroll
    for (int j = 0; j < 4; j++) {
        const __half* q0p = Qg + (size_t)(wq + g)*D_ + 16*j + 2*ctg;
        const __half* q1p = Qg + (size_t)(wq + g + 8)*D_ + 16*j + 2*ctg;
        aq[j][0] = *(const unsigned*)(q0p);
        aq[j][2] = *(const unsigned*)(q0p + 8);
        aq[j][1] = *(const unsigned*)(q1p);
        aq[j][3] = *(const unsigned*)(q1p + 8);
    }

    float m_i[2] = {-1e30f, -1e30f};
    float l_i[2] = {0.f, 0.f};
    float o[8][4];
#pragma unroll
    for (int nf = 0; nf < 8; nf++)
#pragma unroll
        for (int r = 0; r < 4; r++) o[nf][r] = 0.f;

    const int nkt = (q0 >> 6) + 2;
    attn_stage(smc, Kg, Vg, 0, tid);
    attn_stage(smc, Kg, Vg, 1, tid);

#pragma unroll 1
    for (int kt = 0; kt < nkt; kt++) {
        if (kt + 1 < nkt) { CP_WAIT(1); } else { CP_WAIT(0); }
        __syncthreads();
        if (kt + 2 < nkt) attn_stage(smc, Kg, Vg, kt + 2, tid);

        if ((kt << 6) <= wq + 15) {      // per-warp causal tile skip
            const char* Ksb = smc + (kt % 3) * A_STGB;
            const unsigned kbase = (unsigned)__cvta_generic_to_shared(Ksb);
            const unsigned vbase = kbase + KS_B;

            // S = Q K^T : B-frags via ldmatrix.x4 (pair p covers nf=2p,2p+1)
            float s[8][4];
#pragma unroll
            for (int nf = 0; nf < 8; nf++)
#pragma unroll
                for (int r = 0; r < 4; r++) s[nf][r] = 0.f;
#pragma unroll
            for (int j = 0; j < 4; j++) {
#pragma unroll
                for (int p = 0; p < 4; p++) {
                    unsigned q0, q1, q2, q3;
                    ldsm_x4(q0, q1, q2, q3,
                            kbase + (p*16 + lrow_b)*AK_B + 32*j + kh_b*16);
                    unsigned b0[2] = { q0, q1 };
                    unsigned b1[2] = { q2, q3 };
                    mma_f16(s[2*p],   aq[j], b0, s[2*p]);
                    mma_f16(s[2*p+1], aq[j], b1, s[2*p+1]);
                }
            }

            // causal mask (diagonal-overlapping tiles only)
            if ((kt << 6) + 63 > wq) {
#pragma unroll
                for (int nf = 0; nf < 8; nf++) {
                    int col = (kt << 6) + (nf << 3) + (ctg << 1);
                    int r0 = wq + g, r1 = wq + g + 8;
                    if (col     > r0) s[nf][0] = -1e30f;
                    if (col + 1 > r0) s[nf][1] = -1e30f;
                    if (col     > r1) s[nf][2] = -1e30f;
                    if (col + 1 > r1) s[nf][3] = -1e30f;
                }
            }

            // online softmax (exp2 domain); a row lives on lanes 4g..4g+3
#pragma unroll
            for (int rr = 0; rr < 2; rr++) {
                float mx = -1e30f;
#pragma unroll
                for (int nf = 0; nf < 8; nf++)
                    mx = fmaxf(mx, fmaxf(s[nf][rr*2], s[nf][rr*2+1]));
                mx = fmaxf(mx, __shfl_xor_sync(0xffffffffu, mx, 1));
                mx = fmaxf(mx, __shfl_xor_sync(0xffffffffu, mx, 2));
                float mn = fmaxf(m_i[rr], mx);
                float alpha = exp2f(m_i[rr] - mn);
                m_i[rr] = mn;
                float rs = 0.f;
#pragma unroll
                for (int nf = 0; nf < 8; nf++) {
                    float pa = exp2f(s[nf][rr*2]   - mn);
                    float pb = exp2f(s[nf][rr*2+1] - mn);
                    s[nf][rr*2] = pa; s[nf][rr*2+1] = pb;
                    rs += pa + pb;
                }
                rs += __shfl_xor_sync(0xffffffffu, rs, 1);
                rs += __shfl_xor_sync(0xffffffffu, rs, 2);
                l_i[rr] = l_i[rr]*alpha + rs;
#pragma unroll
                for (int nf = 0; nf < 8; nf++) {
                    o[nf][rr*2]   *= alpha;
                    o[nf][rr*2+1] *= alpha;
                }
            }

            // P -> per-warp smem (fp16, plain)
#pragma unroll
            for (int nf = 0; nf < 8; nf++) {
                int off = 16*nf + 4*ctg;
                *(__half2*)(Pw + g*P_B + off) =
                    __floats2half2_rn(s[nf][0], s[nf][1]);
                *(__half2*)(Pw + (g+8)*P_B + off) =
                    __floats2half2_rn(s[nf][2], s[nf][3]);
            }
            __syncwarp();

            // O += P @ V : P a-frags via ldmatrix.x4, V via ldmatrix.x4.trans
#pragma unroll
            for (int j = 0; j < 4; j++) {
                unsigned ap[4];
                ldsm_x4(ap[0], ap[1], ap[2], ap[3],
                        pw_u + lrow_a*P_B + 32*j + kh_a*16);
#pragma unroll
                for (int nfp = 0; nfp < 8; nfp += 2) {
                    unsigned r0, r1, r2, r3;
                    unsigned addr = vbase + (16*j + ldm_row)*AV_B + nfp*16 + ldm_col;
                    ldsm_x4_t(r0, r1, r2, r3, addr);
                    unsigned b0[2] = { r0, r1 };
                    unsigned b1[2] = { r2, r3 };
                    mma_f16(o[nfp],   ap, b0, o[nfp]);
                    mma_f16(o[nfp+1], ap, b1, o[nfp+1]);
                }
            }
        }
    }

    // epilogue: write g_ao fp16 plain (proj GEMM reads natural layout)
    const int b = bh >> 4, h = bh & 15;
    float inv0 = 1.0f / l_i[0], inv1 = 1.0f / l_i[1];
#pragma unroll
    for (int nf = 0; nf < 8; nf++) {
        int off = (h << 6) + (nf << 3) + (ctg << 1);
        size_t base0 = (size_t)(b*T_ + wq + g    )*C_ + off;
        size_t base1 = (size_t)(b*T_ + wq + g + 8)*C_ + off;
        *(__half2*)(g_ao + base0) = __floats2half2_rn(o[nf][0]*inv0, o[nf][1]*inv0);
        *(__half2*)(g_ao + base1) = __floats2half2_rn(o[nf][2]*inv1, o[nf][3]*inv1);
    }
}

// ---------------------------------------------------------------------------
extern "C" void kernel_launch(void* const* d_in, const int* in_sizes, int n_in,
                              void* d_out, int out_size)
{
    const float* x      = (const float*)d_in[0];
    const float* w_qkv  = (const float*)d_in[1];
    const float* b_qkv  = (const float*)d_in[2];
    const float* w_proj = (const float*)d_in[3];
    const float* b_proj = (const float*)d_in[4];
    float* out = (float*)d_out;

    __half *x_p, *wq_p, *wp_p, *ao_p;
    cudaGetSymbolAddress((void**)&x_p,  g_x);
    cudaGetSymbolAddress((void**)&wq_p, g_wq);
    cudaGetSymbolAddress((void**)&wp_p, g_wp);
    cudaGetSymbolAddress((void**)&ao_p, g_ao);

    const int gemm_smem = 3 * G_STGB;                       // 98304
    const int attn_smem = 3 * A_STGB + 8 * 16 * P_B;        // 73728

    cudaFuncSetAttribute(mma_gemm<true>,
                         cudaFuncAttributeMaxDynamicSharedMemorySize, gemm_smem);
    cudaFuncSetAttribute(mma_gemm<false>,
                         cudaFuncAttributeMaxDynamicSharedMemorySize, gemm_smem);
    cudaFuncSetAttribute(attn_mma,
                         cudaFuncAttributeMaxDynamicSharedMemorySize, attn_smem);

    // prepack (one-time per call; memory-bound)
    pack_rows_h<<<M_*C_/16/256, 256>>>(x, x_p);
    pack_wt_h<<<dim3(3*C_/32, C_/32), dim3(32, 8)>>>(w_qkv, wq_p, 3*C_);
    pack_wt_h<<<dim3(C_/32, C_/32),   dim3(32, 8)>>>(w_proj, wp_p, C_);

    dim3 gq(24, 64);   // N=3072/128, M=8192/128
    mma_gemm<true><<<gq, 256, gemm_smem>>>(x_p, wq_p, b_qkv, nullptr);

    dim3 ga(16, 64);   // q-blocks (128 rows), B*H
    attn_mma<<<ga, 256, attn_smem>>>();

    dim3 gp(8, 64);    // N=1024/128, M=8192/128
    mma_gemm<false><<<gp, 256, gemm_smem>>>(ao_p, wp_p, b_proj, out);
}